// round 1
// baseline (speedup 1.0000x reference)
#include <cuda_runtime.h>
#include <cuda_bf16.h>

// Problem constants (from reference): B=128, L=1024, D=2048, f32.
#define PB 128
#define PL 1024
#define PD 2048

#define BLOCK_THREADS 256      // each thread owns one float4 -> 1024 floats of D per block
#define D_CHUNKS (PD / (BLOCK_THREADS * 4))   // = 2
#define ROW_SPLITS 8
#define ROWS_PER_SPLIT (PL / ROW_SPLITS)      // = 128

__global__ void avgpool_var_kernel(const float* __restrict__ feat,
                                   const int* __restrict__ lengths,
                                   float* __restrict__ out) {
    const int b = blockIdx.z;
    int len = lengths[b];
    const int eff = (len > 0) ? len : PL;

    const int r0 = blockIdx.y * ROWS_PER_SPLIT;
    if (r0 >= eff) return;                       // nothing to do for this split
    const int r1 = min(r0 + ROWS_PER_SPLIT, eff);

    // float4 column index this thread owns
    const int d4 = blockIdx.x * BLOCK_THREADS + threadIdx.x;     // 0 .. PD/4-1
    const float4* __restrict__ fp = (const float4*)feat;
    const size_t row_stride4 = PD / 4;
    size_t idx = ((size_t)b * PL + r0) * row_stride4 + d4;

    float4 acc = make_float4(0.f, 0.f, 0.f, 0.f);

    int nrows = r1 - r0;
    #pragma unroll 4
    for (int r = 0; r < nrows; ++r) {
        float4 v = __ldg(&fp[idx]);
        acc.x += v.x; acc.y += v.y; acc.z += v.z; acc.w += v.w;
        idx += row_stride4;
    }

    const float inv = 1.0f / (float)eff;
    float* o = out + (size_t)b * PD + (size_t)d4 * 4;
    atomicAdd(o + 0, acc.x * inv);
    atomicAdd(o + 1, acc.y * inv);
    atomicAdd(o + 2, acc.z * inv);
    atomicAdd(o + 3, acc.w * inv);
}

extern "C" void kernel_launch(void* const* d_in, const int* in_sizes, int n_in,
                              void* d_out, int out_size) {
    const float* feat    = (const float*)d_in[0];
    const int*   lengths = (const int*)d_in[1];
    float*       out     = (float*)d_out;

    // d_out is poisoned; zero it (memset nodes are graph-capturable).
    cudaMemsetAsync(out, 0, (size_t)out_size * sizeof(float));

    dim3 grid(D_CHUNKS, ROW_SPLITS, PB);
    dim3 block(BLOCK_THREADS);
    avgpool_var_kernel<<<grid, block>>>(feat, lengths, out);
}